// round 10
// baseline (speedup 1.0000x reference)
#include <cuda_runtime.h>

// LatentDT: z[n,v] = clamp(min over edges on root->v path of +-(x[n].A[s]), 0, 1)
// At a live split (q>0): qL>0 iff p>0, qR>0 iff p<0 -> exactly ONE child
// survives per level. Stackless root-to-leaf descent, 11 writes per row.
// Output-write-bound; R10 makes the fill fully line-aligned:
// 8 rows/block = 65504 B = 4094 float4 exactly, 16B-aligned per block,
// so no store instruction straddles a cache line (halves L1 wavefronts
// vs the per-row scalar fill whose 4B-aligned rows split ~every store).

#define DEPTH     10
#define NB_SPLIT  1023   // 2^10 - 1
#define NB_NODES  2047   // 2^11 - 1
#define KDIM      128

#define THREADS        256
#define ROWS_PER_BLOCK 8
#define F4_PER_BLOCK   ((ROWS_PER_BLOCK * NB_NODES) / 4)   // 4094 exactly

__global__ void __launch_bounds__(THREADS, 8) latentdt_kernel(
    const float* __restrict__ x,
    const float* __restrict__ A,
    float* __restrict__ out,
    int rows)
{
    const int tid  = threadIdx.x;
    const int lane = tid & 31;
    const int warp = tid >> 5;
    const int row0 = blockIdx.x * ROWS_PER_BLOCK;
    const int row  = row0 + warp;

    const float4* __restrict__ Af4 = reinterpret_cast<const float4*>(A);

    // Issue x-row and A[0] loads BEFORE the fill so their latency hides.
    float4 xv, av;
    if (row < rows) {
        xv = __ldg(reinterpret_cast<const float4*>(x + (size_t)row * KDIM) + lane);
        av = __ldg(Af4 + lane);
    }

    // ---- Block-cooperative aligned float4 zero fill (default policy) ----
    if (row0 + ROWS_PER_BLOCK <= rows) {
        float4* blk = reinterpret_cast<float4*>(out + (size_t)row0 * NB_NODES);
        const float4 z4 = make_float4(0.f, 0.f, 0.f, 0.f);
        #pragma unroll 4
        for (int i = tid; i < F4_PER_BLOCK; i += THREADS) blk[i] = z4;
    } else {
        // tail block (not hit: rows % 8 == 0), scalar fallback
        const size_t base  = (size_t)row0 * NB_NODES;
        const size_t total = (size_t)rows * NB_NODES;
        for (size_t i = base + tid; i < total; i += THREADS) out[i] = 0.0f;
    }
    __syncthreads();   // fill ordered before scatter overwrites

    if (row >= rows) return;

    float* outrow = out + (size_t)row * NB_NODES;
    if (lane == 0) outrow[0] = 1.0f;   // root: clamp(1) = 1

    // ---- Stackless path descent: exactly one survivor per level ----
    int   node = 0;
    float q    = 1.0f;                 // path-min, > 0 while descending

    #pragma unroll
    for (int d = 0; d < DEPTH; ++d) {
        // dot(x_row, A[node]): per-lane float4 FMA + butterfly reduce
        float p = fmaf(xv.x, av.x,
                  fmaf(xv.y, av.y,
                  fmaf(xv.z, av.z, xv.w * av.w)));
        p += __shfl_xor_sync(0xffffffffu, p, 16);
        p += __shfl_xor_sync(0xffffffffu, p, 8);
        p += __shfl_xor_sync(0xffffffffu, p, 4);
        p += __shfl_xor_sync(0xffffffffu, p, 2);
        p += __shfl_xor_sync(0xffffffffu, p, 1);
        // p warp-uniform.

        if (p > 0.0f) {                        // left child survives
            const int cl = 2 * node + 1;
            q = fminf(q, p);                   // <= 1 always
            if (lane == 0) outrow[cl] = q;
            node = cl;
        } else if (p < 0.0f) {                 // right child survives
            const int cr = 2 * node + 2;
            q = fminf(q, -p);
            if (lane == 0) outrow[cr] = q;
            node = cr;
        } else {
            break;                             // p == 0: both children clamp to 0
        }

        if (d < DEPTH - 1)                     // next level's A row
            av = __ldg(Af4 + (size_t)node * (KDIM / 4) + lane);
    }
}

extern "C" void kernel_launch(void* const* d_in, const int* in_sizes, int n_in,
                              void* d_out, int out_size)
{
    const float* x = (const float*)d_in[0];   // [rows, 128]
    const float* A = (const float*)d_in[1];   // [1023, 128]
    float* out = (float*)d_out;               // [rows, 2047]

    const int rows = out_size / NB_NODES;     // 32768

    const int blocks = (rows + ROWS_PER_BLOCK - 1) / ROWS_PER_BLOCK;
    latentdt_kernel<<<blocks, THREADS>>>(x, A, out, rows);
}

// round 13
// speedup vs baseline: 1.0841x; 1.0841x over previous
#include <cuda_runtime.h>

// LatentDT: z[n,v] = clamp(min over edges on root->v path of +-(x[n].A[s]), 0, 1)
// KEY: at a live split (q>0), qL>0 iff p>0 and qR>0 iff p<0 -> exactly ONE
// child survives each level. The "tree DFS" is a single root-to-leaf path:
// stackless, exactly DEPTH levels, 11 writes per row.
//
// FINAL (R9 config, measured best): per-warp scalar fill paces DRAM writes
// best (4.33 TB/s); fused kernel time equals the isolated pure-memset time
// (~53 us), so the path descent is fully hidden -> at the write roofline.

#define DEPTH     10
#define NB_SPLIT  1023   // 2^10 - 1
#define NB_NODES  2047   // 2^11 - 1
#define KDIM      128

__global__ void __launch_bounds__(256, 8) latentdt_kernel(
    const float* __restrict__ x,
    const float* __restrict__ A,
    float* __restrict__ out,
    int rows)
{
    const int row  = (blockIdx.x * blockDim.x + threadIdx.x) >> 5;
    const int lane = threadIdx.x & 31;
    if (row >= rows) return;

    // x row: 128 floats, 4 per lane (512B, coalesced).
    const float4 xv = __ldg(reinterpret_cast<const float4*>(
                                x + (size_t)row * KDIM) + lane);

    const float4* __restrict__ Af4 = reinterpret_cast<const float4*>(A);

    // Prefetch A[0] so the root dot's load latency hides under the fill.
    float4 av = __ldg(Af4 + lane);

    float* outrow = out + (size_t)row * NB_NODES;

    // Per-warp scalar zero fill of own row (measured-best DRAM pacing).
    for (int idx = lane; idx < NB_NODES; idx += 32) outrow[idx] = 0.0f;
    __syncwarp();                      // order fill before scatter overwrites
    if (lane == 0) outrow[0] = 1.0f;   // root: clamp(1) = 1

    // ---- Stackless path descent: exactly one survivor per level ----
    int   node = 0;
    float q    = 1.0f;                 // path-min, always > 0 while looping

    #pragma unroll
    for (int d = 0; d < DEPTH; ++d) {
        // dot(x_row, A[node]): per-lane float4 FMA + butterfly reduce
        float p = fmaf(xv.x, av.x,
                  fmaf(xv.y, av.y,
                  fmaf(xv.z, av.z, xv.w * av.w)));
        p += __shfl_xor_sync(0xffffffffu, p, 16);
        p += __shfl_xor_sync(0xffffffffu, p, 8);
        p += __shfl_xor_sync(0xffffffffu, p, 4);
        p += __shfl_xor_sync(0xffffffffu, p, 2);
        p += __shfl_xor_sync(0xffffffffu, p, 1);
        // p warp-uniform.

        if (p > 0.0f) {                        // left child survives
            const int cl = 2 * node + 1;
            q = fminf(q, p);                   // <= 1 always
            if (lane == 0) outrow[cl] = q;
            node = cl;
        } else if (p < 0.0f) {                 // right child survives
            const int cr = 2 * node + 2;
            q = fminf(q, -p);
            if (lane == 0) outrow[cr] = q;
            node = cr;
        } else {
            break;                             // p == 0: both children clamp to 0
        }

        if (d < DEPTH - 1)                     // load next level's A row
            av = __ldg(Af4 + (size_t)node * (KDIM / 4) + lane);
    }
}

extern "C" void kernel_launch(void* const* d_in, const int* in_sizes, int n_in,
                              void* d_out, int out_size)
{
    const float* x = (const float*)d_in[0];   // [rows, 128]
    const float* A = (const float*)d_in[1];   // [1023, 128]
    float* out = (float*)d_out;               // [rows, 2047]

    const int rows = out_size / NB_NODES;     // 32768

    const int threads = 256;                  // 8 warps/block, 1 row/warp
    const int blocks = (rows + 7) / 8;
    latentdt_kernel<<<blocks, threads>>>(x, A, out, rows);
}